// round 3
// baseline (speedup 1.0000x reference)
#include <cuda_runtime.h>
#include <cuda_bf16.h>
#include <math.h>

// PolarVoxelizer R3: single fused persistent kernel.
//  Phase 1 (warp-specialized): warps 0-5 zero the output (HBM-write bound),
//  warps 6-7 compute per-point linear indices into __device__ scratch
//  (latency bound) -- the two run concurrently, hiding compute under zeroing.
//  Grid-wide software barrier (monotonic ticket counter, graph-replay safe).
//  Phase 2: all warps scatter 1.0f from scratch.

#define Z_DEPTH   100
#define HALF_FOV  1.134f
#define R_MIN_C   2.7f
#define R_MAX_C   165.0f
#define MAX_RB    512
#define MAX_AB    256
#define MAX_PTS   (1 << 20)

__device__ int g_lin[MAX_PTS];          // per-point linear index or -1
__device__ unsigned int g_ctr = 0;       // barrier ticket counter (monotonic)

// Exact searchsorted(side='left') given an approximate starting index.
__device__ __forceinline__ int lb_fixup(const float* __restrict__ a, int n, float v, int idx) {
    idx = min(max(idx, 0), n);
    while (idx > 0 && a[idx - 1] >= v) --idx;
    while (idx < n && a[idx] < v) ++idx;
    return idx;
}

__global__ __launch_bounds__(256) void polar_voxelize_fused(
    const float4* __restrict__ lidars4,    // batch-0 points as float4 stream
    const float* __restrict__ r_bins,
    const float* __restrict__ angle_bins,
    float* __restrict__ out,
    int out_n4,                            // out_size / 4 (float4 count)
    int npts, int n_per_s, int num_r, int num_a,
    float a0, float inv_astep,             // angle uniform-grid guess params
    float log2_rmin, float inv_log2_1pd)   // radius geometric-grid guess params
{
    __shared__ float s_r[MAX_RB];
    __shared__ float s_a[MAX_AB];
    for (int i = threadIdx.x; i < num_r; i += blockDim.x) s_r[i] = r_bins[i];
    for (int i = threadIdx.x; i < num_a; i += blockDim.x) s_a[i] = angle_bins[i];
    __syncthreads();

    const int warp = threadIdx.x >> 5;
    const int lane = threadIdx.x & 31;

    if (warp >= 6) {
        // ---- point warps (2 per block): compute bin indices -> scratch ----
        int ptid = (blockIdx.x * 2 + (warp - 6)) * 32 + lane;
        int pstride = gridDim.x * 64;
        int nchunks = (npts + 3) >> 2;
        for (int c = ptid; c < nchunks; c += pstride) {
            int base = c * 4;
            int v4 = c * 3;
            float4 q0 = lidars4[v4 + 0];
            float4 q1 = lidars4[v4 + 1];
            float4 q2 = lidars4[v4 + 2];
            float px[4] = {q0.x, q0.w, q1.z, q2.y};
            float py[4] = {q0.y, q1.x, q1.w, q2.z};
            float pz[4] = {q0.z, q1.y, q2.x, q2.w};
            #pragma unroll
            for (int k = 0; k < 4; ++k) {
                int i = base + k;
                if (i >= npts) break;
                float x = px[k], y = py[k], z = pz[k];
                int lin = -1;

                // radius: bit-exact vs XLA f32
                float radius = __fsqrt_rn(__fadd_rn(__fmul_rn(x, x), __fmul_rn(y, y)));
                if ((radius < R_MAX_C) && (radius > R_MIN_C)) {
                    // angle: atan2f fast path, double refine near boundaries
                    float v = atan2f(y, x);
                    float eps = fmaxf(fabsf(v) * 1.0e-6f, 1.0e-7f);

                    int yg0 = (int)floorf((v - a0) * inv_astep);
                    int yg = lb_fixup(s_a, num_a, v, yg0);

                    bool near = (fabsf(fabsf(v) - HALF_FOV) <= eps);
                    if (yg < num_a && fabsf(v - s_a[yg])     <= eps) near = true;
                    if (yg > 0     && fabsf(v - s_a[yg - 1]) <= eps) near = true;
                    if (near) {
                        v = (float)atan2((double)y, (double)x);
                        yg = lb_fixup(s_a, num_a, v, yg);
                    }
                    if (fabsf(v) < HALF_FOV) {
                        int xg0 = (int)floorf((__log2f(radius) - log2_rmin) * inv_log2_1pd);
                        int xg = lb_fixup(s_r, num_r, radius, xg0);
                        int zg = (int)floorf(__fdiv_rn(__fsub_rn(z, -2.0f), 0.2f));
                        int s = i / n_per_s;
                        lin = ((s * Z_DEPTH + zg) * num_a + yg) * num_r + xg;
                    }
                }
                g_lin[i] = lin;
            }
        }
    } else {
        // ---- zero warps (6 per block): stream-zero the output ----
        int ztid = (blockIdx.x * 6 + warp) * 32 + lane;
        int zstride = gridDim.x * 192;
        float4 zz = make_float4(0.f, 0.f, 0.f, 0.f);
        float4* o4 = (float4*)out;
        for (int j = ztid; j < out_n4; j += zstride) o4[j] = zz;
    }

    // ---- grid-wide barrier (replay-safe monotonic ticket) ----
    __threadfence();
    __syncthreads();
    if (threadIdx.x == 0) {
        unsigned int t = atomicAdd(&g_ctr, 1u);
        unsigned int target = (t / gridDim.x + 1u) * gridDim.x;
        while (atomicAdd(&g_ctr, 0u) < target) __nanosleep(128);
    }
    __syncthreads();
    __threadfence();

    // ---- phase 2: scatter 1.0f from scratch ----
    int tid = blockIdx.x * blockDim.x + threadIdx.x;
    int nthreads = gridDim.x * blockDim.x;
    for (int i = tid; i < npts; i += nthreads) {
        int lin = g_lin[i];
        if (lin >= 0) out[lin] = 1.0f;
    }
}

extern "C" void kernel_launch(void* const* d_in, const int* in_sizes, int n_in,
                              void* d_out, int out_size) {
    const float* lidars     = (const float*)d_in[0];
    const float* r_bins     = (const float*)d_in[1];
    const float* angle_bins = (const float*)d_in[2];
    float* out = (float*)d_out;

    const int B = 2;  // output keeps only batch 0
    int num_r = in_sizes[1];
    int num_a = in_sizes[2];
    int npts  = in_sizes[0] / (3 * B);
    int S     = out_size / (Z_DEPTH * num_a * num_r);
    int n_per_s = npts / S;

    // Analytic grid params (guesses only; exactness via lb_fixup)
    double fov = 2.268;
    float a0 = (float)(-fov / 2.0);
    float inv_astep = (float)((num_a - 1) / fov);
    double delta = pow((165.0 + 0.0001) / 2.7, 1.0 / (double)(num_r - 1)) - 1.0;
    float log2_rmin = (float)(log(2.7) / log(2.0));
    float inv_log2_1pd = (float)(log(2.0) / log(1.0 + delta));

    // Co-resident grid: SMs * occupancy (software barrier requires this)
    int dev = 0;
    cudaGetDevice(&dev);
    int sms = 148;
    cudaDeviceGetAttribute(&sms, cudaDevAttrMultiProcessorCount, dev);
    int occ = 1;
    cudaOccupancyMaxActiveBlocksPerMultiprocessor(&occ, polar_voxelize_fused, 256, 0);
    if (occ < 1) occ = 1;
    if (occ > 32) occ = 32;
    int grid = sms * occ;

    polar_voxelize_fused<<<grid, 256>>>(
        (const float4*)lidars, r_bins, angle_bins, out,
        out_size / 4, npts, n_per_s, num_r, num_a,
        a0, inv_astep, log2_rmin, inv_log2_1pd);
}

// round 4
// speedup vs baseline: 1.4869x; 1.4869x over previous
#include <cuda_runtime.h>
#include <cuda_bf16.h>
#include <math.h>

// PolarVoxelizer R4: 3-kernel graph with PDL overlap.
//   K1 k_indices : per-point bin indices -> g_lin scratch (latency-bound)
//   K2 k_zero    : float4 stream-zero of output (HBM-bound), PDL-overlapped w/ K1
//   K3 k_scatter : out[g_lin[i]] = 1.0f, normal launch (waits K1 & K2)

#define Z_DEPTH   100
#define HALF_FOV  1.134f
#define R_MIN_C   2.7f
#define R_MAX_C   165.0f
#define MAX_RB    512
#define MAX_AB    256
#define MAX_PTS   (1 << 20)

__device__ int g_lin[MAX_PTS];   // per-point linear index or -1

// Exact searchsorted(side='left') given an approximate starting index.
__device__ __forceinline__ int lb_fixup(const float* __restrict__ a, int n, float v, int idx) {
    idx = min(max(idx, 0), n);
    while (idx > 0 && a[idx - 1] >= v) --idx;
    while (idx < n && a[idx] < v) ++idx;
    return idx;
}

__global__ __launch_bounds__(256) void k_indices(
    const float4* __restrict__ lidars4,
    const float* __restrict__ r_bins,
    const float* __restrict__ angle_bins,
    int npts, int n_per_s, int num_r, int num_a,
    float a0, float inv_astep,
    float log2_rmin, float inv_log2_1pd)
{
#if __CUDA_ARCH__ >= 900
    cudaTriggerProgrammaticLaunchCompletion();   // let K2 co-schedule now
#endif
    __shared__ float s_r[MAX_RB];
    __shared__ float s_a[MAX_AB];
    for (int i = threadIdx.x; i < num_r; i += blockDim.x) s_r[i] = r_bins[i];
    for (int i = threadIdx.x; i < num_a; i += blockDim.x) s_a[i] = angle_bins[i];
    __syncthreads();

    int c = blockIdx.x * blockDim.x + threadIdx.x;   // chunk of 4 points
    int nchunks = (npts + 3) >> 2;
    if (c >= nchunks) return;

    int base = c * 4;
    int v4 = c * 3;
    float4 q0 = lidars4[v4 + 0];
    float4 q1 = lidars4[v4 + 1];
    float4 q2 = lidars4[v4 + 2];
    float px[4] = {q0.x, q0.w, q1.z, q2.y};
    float py[4] = {q0.y, q1.x, q1.w, q2.z};
    float pz[4] = {q0.z, q1.y, q2.x, q2.w};

    #pragma unroll
    for (int k = 0; k < 4; ++k) {
        int i = base + k;
        if (i >= npts) break;
        float x = px[k], y = py[k], z = pz[k];
        int lin = -1;

        // radius: bit-exact vs XLA f32 (no FMA contraction, IEEE sqrt)
        float radius = __fsqrt_rn(__fadd_rn(__fmul_rn(x, x), __fmul_rn(y, y)));
        if ((radius < R_MAX_C) && (radius > R_MIN_C)) {
            // angle: atan2f fast path, double refine near decision boundaries
            float v = atan2f(y, x);
            float eps = fmaxf(fabsf(v) * 1.0e-6f, 1.0e-7f);

            int yg0 = (int)floorf((v - a0) * inv_astep);
            int yg = lb_fixup(s_a, num_a, v, yg0);

            bool near = (fabsf(fabsf(v) - HALF_FOV) <= eps);
            if (yg < num_a && fabsf(v - s_a[yg])     <= eps) near = true;
            if (yg > 0     && fabsf(v - s_a[yg - 1]) <= eps) near = true;
            if (near) {
                v = (float)atan2((double)y, (double)x);
                yg = lb_fixup(s_a, num_a, v, yg);
            }
            if (fabsf(v) < HALF_FOV) {
                int xg0 = (int)floorf((__log2f(radius) - log2_rmin) * inv_log2_1pd);
                int xg = lb_fixup(s_r, num_r, radius, xg0);
                int zg = (int)floorf(__fdiv_rn(__fsub_rn(z, -2.0f), 0.2f));
                int s = i / n_per_s;
                lin = ((s * Z_DEPTH + zg) * num_a + yg) * num_r + xg;
            }
        }
        g_lin[i] = lin;
    }
}

__global__ __launch_bounds__(256) void k_zero(float4* __restrict__ out4, int n4)
{
    int tid = blockIdx.x * blockDim.x + threadIdx.x;
    int stride = gridDim.x * blockDim.x;
    float4 z = make_float4(0.f, 0.f, 0.f, 0.f);
    for (int j = tid; j < n4; j += stride) out4[j] = z;
}

__global__ __launch_bounds__(256) void k_scatter(float* __restrict__ out, int npts)
{
    int i = blockIdx.x * blockDim.x + threadIdx.x;
    if (i >= npts) return;
    int lin = g_lin[i];
    if (lin >= 0) out[lin] = 1.0f;
}

extern "C" void kernel_launch(void* const* d_in, const int* in_sizes, int n_in,
                              void* d_out, int out_size) {
    const float* lidars     = (const float*)d_in[0];
    const float* r_bins     = (const float*)d_in[1];
    const float* angle_bins = (const float*)d_in[2];
    float* out = (float*)d_out;

    const int B = 2;  // output keeps only batch 0
    int num_r = in_sizes[1];
    int num_a = in_sizes[2];
    int npts  = in_sizes[0] / (3 * B);
    int S     = out_size / (Z_DEPTH * num_a * num_r);
    int n_per_s = npts / S;

    // Analytic grid params (guesses only; exactness via lb_fixup)
    double fov = 2.268;
    float a0 = (float)(-fov / 2.0);
    float inv_astep = (float)((num_a - 1) / fov);
    double delta = pow((165.0 + 0.0001) / 2.7, 1.0 / (double)(num_r - 1)) - 1.0;
    float log2_rmin = (float)(log(2.7) / log(2.0));
    float inv_log2_1pd = (float)(log(2.0) / log(1.0 + delta));

    // --- K1: index compute (primary; triggers early for PDL overlap) ---
    int nchunks = (npts + 3) / 4;
    int k1_blocks = (nchunks + 255) / 256;
    k_indices<<<k1_blocks, 256>>>(
        (const float4*)lidars, r_bins, angle_bins,
        npts, n_per_s, num_r, num_a,
        a0, inv_astep, log2_rmin, inv_log2_1pd);

    // --- K2: zero output, PDL-overlapped with K1 (independent memory) ---
    {
        int n4 = out_size / 4;
        int k2_blocks = 148 * 8;
        cudaLaunchConfig_t cfg = {};
        cfg.gridDim = dim3(k2_blocks, 1, 1);
        cfg.blockDim = dim3(256, 1, 1);
        cfg.dynamicSmemBytes = 0;
        cfg.stream = 0;
        cudaLaunchAttribute attr[1];
        attr[0].id = cudaLaunchAttributeProgrammaticStreamSerialization;
        attr[0].val.programmaticStreamSerializationAllowed = 1;
        cfg.attrs = attr;
        cfg.numAttrs = 1;
        float4* out4 = (float4*)out;
        cudaLaunchKernelEx(&cfg, k_zero, out4, n4);
    }

    // --- K3: scatter (normal launch: waits for BOTH K1 and K2) ---
    int k3_blocks = (npts + 255) / 256;
    k_scatter<<<k3_blocks, 256>>>(out, npts);
}